// round 1
// baseline (speedup 1.0000x reference)
#include <cuda_runtime.h>
#include <cstdint>

#define N_USERS 30000
#define N_ENT   70000
#define N_NODES 100000
#define D_IN    64
#define N_EDGES 1600000

// Scratch: ego embeddings (updated in place per layer) and side (spmm accumulator).
// float4 for 16B alignment (needed by red.v4 and vectorized loads).
__device__ float4 g_ego4[N_NODES * 16];   // N x 64 floats
__device__ float4 g_side4[N_NODES * 16];  // N x 64 floats

// ---------------------------------------------------------------------------
// Kernel 1: build ego0 = concat(user_tab, entity_tab); zero side; write out[:,0:64]
// ---------------------------------------------------------------------------
__global__ __launch_bounds__(256) void k_init(
    const float4* __restrict__ user4,   // [30000*16]
    const float4* __restrict__ ent4,    // [70000*16]
    float4* __restrict__ out4)          // [N*40]  (160 floats per row)
{
    int idx = blockIdx.x * blockDim.x + threadIdx.x;
    if (idx >= N_NODES * 16) return;
    int row = idx >> 4;
    int part = idx & 15;
    float4 v = (row < N_USERS) ? user4[row * 16 + part]
                               : ent4[(row - N_USERS) * 16 + part];
    g_ego4[idx] = v;
    g_side4[idx] = make_float4(0.f, 0.f, 0.f, 0.f);
    out4[row * 40 + part] = v;  // columns [0,64)
}

// ---------------------------------------------------------------------------
// Kernel 2: SpMM  side[r] += vals[e] * ego[c]   (COO, vector red.add.v4.f32)
// 16 threads per edge, each handles 4 dims.
// ---------------------------------------------------------------------------
__global__ __launch_bounds__(256) void k_spmm(
    const int* __restrict__ rows,
    const int* __restrict__ cols,
    const float* __restrict__ vals)
{
    long long gid = (long long)blockIdx.x * blockDim.x + threadIdx.x;
    if (gid >= (long long)N_EDGES * 16) return;
    int e = (int)(gid >> 4);
    int part = (int)(gid & 15);
    int c = cols[e];
    int r = rows[e];
    float v = vals[e];
    float4 x = g_ego4[c * 16 + part];
    float4* dst = &g_side4[r * 16 + part];
    asm volatile(
        "red.relaxed.gpu.global.add.v4.f32 [%0], {%1, %2, %3, %4};"
        :: "l"(dst), "f"(v * x.x), "f"(v * x.y), "f"(v * x.z), "f"(v * x.w)
        : "memory");
}

// ---------------------------------------------------------------------------
// Kernel 3: bi-interaction layer 1 (64 -> 64), l2norm, write ego (in place)
// and out[:,64:128]. Also zeros side for the second SpMM.
// One warp per row, 8 warps per block, grid-stride over rows.
// ---------------------------------------------------------------------------
__global__ __launch_bounds__(256) void k_bi1(
    const float* __restrict__ W1,  // [64,64] row-major
    const float* __restrict__ b1,  // [64]
    const float* __restrict__ W2,  // [64,64]
    const float* __restrict__ b2,  // [64]
    float* __restrict__ out)       // [N,160]
{
    __shared__ float sW1[64 * 64];
    __shared__ float sW2[64 * 64];
    __shared__ float a_sh[8][64];
    __shared__ float m_sh[8][64];

    int tid = threadIdx.x;
    for (int i = tid; i < 64 * 64; i += 256) {
        sW1[i] = W1[i];
        sW2[i] = W2[i];
    }
    __syncthreads();

    int warp = tid >> 5;
    int lane = tid & 31;
    int j0 = lane;
    int j1 = lane + 32;
    float bias10 = b1[j0], bias11 = b1[j1];
    float bias20 = b2[j0], bias21 = b2[j1];

    float* ego = (float*)g_ego4;
    float* side = (float*)g_side4;

    int warps_total = gridDim.x * 8;
    for (int r = blockIdx.x * 8 + warp; r < N_NODES; r += warps_total) {
        float2 e = ((const float2*)ego)[r * 32 + lane];
        float2 s = ((const float2*)side)[r * 32 + lane];
        a_sh[warp][2 * lane]     = e.x + s.x;
        a_sh[warp][2 * lane + 1] = e.y + s.y;
        m_sh[warp][2 * lane]     = e.x * s.x;
        m_sh[warp][2 * lane + 1] = e.y * s.y;
        // zero side for next spmm pass
        ((float2*)side)[r * 32 + lane] = make_float2(0.f, 0.f);
        __syncwarp();

        float acc10 = bias10, acc11 = bias11;
        float acc20 = bias20, acc21 = bias21;
        #pragma unroll
        for (int k = 0; k < 64; k++) {
            float av = a_sh[warp][k];
            float mv = m_sh[warp][k];
            acc10 += av * sW1[k * 64 + j0];
            acc11 += av * sW1[k * 64 + j1];
            acc20 += mv * sW2[k * 64 + j0];
            acc21 += mv * sW2[k * 64 + j1];
        }
        // leaky relu (slope .01) and sum
        float h0 = (acc10 > 0.f ? acc10 : 0.01f * acc10)
                 + (acc20 > 0.f ? acc20 : 0.01f * acc20);
        float h1 = (acc11 > 0.f ? acc11 : 0.01f * acc11)
                 + (acc21 > 0.f ? acc21 : 0.01f * acc21);
        // l2 norm over the 64 outputs
        float ss = h0 * h0 + h1 * h1;
        #pragma unroll
        for (int off = 16; off > 0; off >>= 1)
            ss += __shfl_xor_sync(0xFFFFFFFFu, ss, off);
        float nrm = sqrtf(ss);
        float inv = 1.f / fmaxf(nrm, 1e-12f);
        h0 *= inv; h1 *= inv;

        ego[r * 64 + j0] = h0;
        ego[r * 64 + j1] = h1;
        out[r * 160 + 64 + j0] = h0;
        out[r * 160 + 64 + j1] = h1;
        __syncwarp();
    }
}

// ---------------------------------------------------------------------------
// Kernel 4: bi-interaction layer 2 (64 -> 32), l2norm, write out[:,128:160]
// ---------------------------------------------------------------------------
__global__ __launch_bounds__(256) void k_bi2(
    const float* __restrict__ W1,  // [64,32]
    const float* __restrict__ b1,  // [32]
    const float* __restrict__ W2,  // [64,32]
    const float* __restrict__ b2,  // [32]
    float* __restrict__ out)       // [N,160]
{
    __shared__ float sW1[64 * 32];
    __shared__ float sW2[64 * 32];
    __shared__ float a_sh[8][64];
    __shared__ float m_sh[8][64];

    int tid = threadIdx.x;
    for (int i = tid; i < 64 * 32; i += 256) {
        sW1[i] = W1[i];
        sW2[i] = W2[i];
    }
    __syncthreads();

    int warp = tid >> 5;
    int lane = tid & 31;
    float bias1 = b1[lane];
    float bias2 = b2[lane];

    const float* ego = (const float*)g_ego4;
    const float* side = (const float*)g_side4;

    int warps_total = gridDim.x * 8;
    for (int r = blockIdx.x * 8 + warp; r < N_NODES; r += warps_total) {
        float2 e = ((const float2*)ego)[r * 32 + lane];
        float2 s = ((const float2*)side)[r * 32 + lane];
        a_sh[warp][2 * lane]     = e.x + s.x;
        a_sh[warp][2 * lane + 1] = e.y + s.y;
        m_sh[warp][2 * lane]     = e.x * s.x;
        m_sh[warp][2 * lane + 1] = e.y * s.y;
        __syncwarp();

        float acc1 = bias1, acc2 = bias2;
        #pragma unroll
        for (int k = 0; k < 64; k++) {
            acc1 += a_sh[warp][k] * sW1[k * 32 + lane];
            acc2 += m_sh[warp][k] * sW2[k * 32 + lane];
        }
        float h = (acc1 > 0.f ? acc1 : 0.01f * acc1)
                + (acc2 > 0.f ? acc2 : 0.01f * acc2);
        float ss = h * h;
        #pragma unroll
        for (int off = 16; off > 0; off >>= 1)
            ss += __shfl_xor_sync(0xFFFFFFFFu, ss, off);
        float nrm = sqrtf(ss);
        float inv = 1.f / fmaxf(nrm, 1e-12f);
        out[r * 160 + 128 + lane] = h * inv;
        __syncwarp();
    }
}

// ---------------------------------------------------------------------------
extern "C" void kernel_launch(void* const* d_in, const int* in_sizes, int n_in,
                              void* d_out, int out_size)
{
    const float* user_tab = (const float*)d_in[0];
    const float* entity_tab = (const float*)d_in[1];
    const float* A_vals = (const float*)d_in[2];
    const float* W1_1 = (const float*)d_in[3];
    const float* b1_1 = (const float*)d_in[4];
    const float* W2_1 = (const float*)d_in[5];
    const float* b2_1 = (const float*)d_in[6];
    const float* W1_2 = (const float*)d_in[7];
    const float* b1_2 = (const float*)d_in[8];
    const float* W2_2 = (const float*)d_in[9];
    const float* b2_2 = (const float*)d_in[10];
    const int* A_rows = (const int*)d_in[11];
    const int* A_cols = (const int*)d_in[12];
    float* out = (float*)d_out;

    // 1. init: ego0, zero side, out[:,0:64]
    {
        int total = N_NODES * 16;
        k_init<<<(total + 255) / 256, 256>>>(
            (const float4*)user_tab, (const float4*)entity_tab, (float4*)out);
    }
    // 2. spmm 1: side = A @ ego0
    {
        long long total = (long long)N_EDGES * 16;
        int grid = (int)((total + 255) / 256);
        k_spmm<<<grid, 256>>>(A_rows, A_cols, A_vals);
    }
    // 3. bi layer 1 (also zeros side)
    k_bi1<<<888, 256>>>(W1_1, b1_1, W2_1, b2_1, out);
    // 4. spmm 2: side = A @ ego1
    {
        long long total = (long long)N_EDGES * 16;
        int grid = (int)((total + 255) / 256);
        k_spmm<<<grid, 256>>>(A_rows, A_cols, A_vals);
    }
    // 5. bi layer 2
    k_bi2<<<1184, 256>>>(W1_2, b1_2, W2_2, b2_2, out);
}

// round 2
// speedup vs baseline: 1.0752x; 1.0752x over previous
#include <cuda_runtime.h>
#include <cstdint>

#define N_USERS 30000
#define N_ENT   70000
#define N_NODES 100000
#define N_EDGES 1600000

// Scratch: ego embeddings (updated in place per layer) and side (spmm accumulator).
__device__ float4 g_ego4[N_NODES * 16];   // N x 64 floats
__device__ float4 g_side4[N_NODES * 16];  // N x 64 floats

// ---------------------------------------------------------------------------
// Kernel 1: ego0 = concat(user_tab, entity_tab); zero side; out[:,0:64]
// ---------------------------------------------------------------------------
__global__ __launch_bounds__(256) void k_init(
    const float4* __restrict__ user4,
    const float4* __restrict__ ent4,
    float4* __restrict__ out4)          // 40 float4 per row (160 floats)
{
    int idx = blockIdx.x * blockDim.x + threadIdx.x;
    if (idx >= N_NODES * 16) return;
    int row = idx >> 4;
    int part = idx & 15;
    float4 v = (row < N_USERS) ? user4[row * 16 + part]
                               : ent4[(row - N_USERS) * 16 + part];
    g_ego4[idx] = v;
    g_side4[idx] = make_float4(0.f, 0.f, 0.f, 0.f);
    out4[row * 40 + part] = v;
}

// ---------------------------------------------------------------------------
// Kernel 2: SpMM  side[r] += vals[e] * ego[c]   (COO, vector red.add.v4.f32)
// 8 threads per edge, each thread handles 8 dims (2x float4).
// ---------------------------------------------------------------------------
__global__ __launch_bounds__(256) void k_spmm(
    const int* __restrict__ rows,
    const int* __restrict__ cols,
    const float* __restrict__ vals)
{
    long long gid = (long long)blockIdx.x * blockDim.x + threadIdx.x;
    if (gid >= (long long)N_EDGES * 8) return;
    int e = (int)(gid >> 3);
    int part = (int)(gid & 7);          // which pair of float4s
    int c = cols[e];
    int r = rows[e];
    float v = vals[e];
    const float4* src = &g_ego4[c * 16 + part * 2];
    float4 x0 = src[0];
    float4 x1 = src[1];
    float4* dst = &g_side4[r * 16 + part * 2];
    asm volatile(
        "red.relaxed.gpu.global.add.v4.f32 [%0], {%1, %2, %3, %4};"
        :: "l"(dst), "f"(v * x0.x), "f"(v * x0.y), "f"(v * x0.z), "f"(v * x0.w)
        : "memory");
    asm volatile(
        "red.relaxed.gpu.global.add.v4.f32 [%0], {%1, %2, %3, %4};"
        :: "l"(dst + 1), "f"(v * x1.x), "f"(v * x1.y), "f"(v * x1.z), "f"(v * x1.w)
        : "memory");
}

// ---------------------------------------------------------------------------
// Kernel 3: bi-interaction layer 1 (64 -> 64), l2norm, updates ego in place,
// writes out[:,64:128], zeros side. One warp computes 4 rows.
// Lane j0=2*lane, j1=2*lane+1 output columns -> LDS.64 weight loads.
// ---------------------------------------------------------------------------
__global__ __launch_bounds__(256) void k_bi1(
    const float* __restrict__ W1,  // [64,64]
    const float* __restrict__ b1,
    const float* __restrict__ W2,  // [64,64]
    const float* __restrict__ b2,
    float* __restrict__ out)       // [N,160]
{
    __shared__ float sW1[64 * 64];
    __shared__ float sW2[64 * 64];
    __shared__ float2 am[8][4][64];   // [warp][row][k] = (ego+side, ego*side)

    int tid = threadIdx.x;
    for (int i = tid; i < 64 * 64; i += 256) {
        sW1[i] = W1[i];
        sW2[i] = W2[i];
    }
    __syncthreads();

    int warp = tid >> 5;
    int lane = tid & 31;
    int j0 = 2 * lane;

    float2* ego2 = (float2*)g_ego4;
    float2* side2 = (float2*)g_side4;

    int rbase = (blockIdx.x * 8 + warp) * 4;

    // stage 4 rows of (a, m); zero side for the next spmm
    #pragma unroll
    for (int rr = 0; rr < 4; rr++) {
        int r = rbase + rr;
        if (r < N_NODES) {
            float2 e = ego2[r * 32 + lane];
            float2 s = side2[r * 32 + lane];
            am[warp][rr][2 * lane]     = make_float2(e.x + s.x, e.x * s.x);
            am[warp][rr][2 * lane + 1] = make_float2(e.y + s.y, e.y * s.y);
            side2[r * 32 + lane] = make_float2(0.f, 0.f);
        }
    }
    __syncwarp();

    float b1x = b1[j0], b1y = b1[j0 + 1];
    float b2x = b2[j0], b2y = b2[j0 + 1];
    float acc1x[4], acc1y[4], acc2x[4], acc2y[4];
    #pragma unroll
    for (int rr = 0; rr < 4; rr++) {
        acc1x[rr] = b1x; acc1y[rr] = b1y;
        acc2x[rr] = b2x; acc2y[rr] = b2y;
    }

    #pragma unroll 8
    for (int k = 0; k < 64; k++) {
        float2 w1 = *(const float2*)(sW1 + k * 64 + j0);
        float2 w2 = *(const float2*)(sW2 + k * 64 + j0);
        #pragma unroll
        for (int rr = 0; rr < 4; rr++) {
            float2 v = am[warp][rr][k];
            acc1x[rr] += v.x * w1.x;
            acc1y[rr] += v.x * w1.y;
            acc2x[rr] += v.y * w2.x;
            acc2y[rr] += v.y * w2.y;
        }
    }

    #pragma unroll
    for (int rr = 0; rr < 4; rr++) {
        int r = rbase + rr;
        if (r >= N_NODES) break;
        float h0 = (acc1x[rr] > 0.f ? acc1x[rr] : 0.01f * acc1x[rr])
                 + (acc2x[rr] > 0.f ? acc2x[rr] : 0.01f * acc2x[rr]);
        float h1 = (acc1y[rr] > 0.f ? acc1y[rr] : 0.01f * acc1y[rr])
                 + (acc2y[rr] > 0.f ? acc2y[rr] : 0.01f * acc2y[rr]);
        float ss = h0 * h0 + h1 * h1;
        #pragma unroll
        for (int off = 16; off > 0; off >>= 1)
            ss += __shfl_xor_sync(0xFFFFFFFFu, ss, off);
        float inv = 1.f / fmaxf(sqrtf(ss), 1e-12f);
        h0 *= inv; h1 *= inv;
        ego2[r * 32 + lane] = make_float2(h0, h1);
        ((float2*)out)[r * 80 + 32 + lane] = make_float2(h0, h1);
    }
}

// ---------------------------------------------------------------------------
// Kernel 4: bi-interaction layer 2 (64 -> 32), l2norm, out[:,128:160].
// One warp computes 4 rows; lane = output column.
// ---------------------------------------------------------------------------
__global__ __launch_bounds__(256) void k_bi2(
    const float* __restrict__ W1,  // [64,32]
    const float* __restrict__ b1,
    const float* __restrict__ W2,  // [64,32]
    const float* __restrict__ b2,
    float* __restrict__ out)       // [N,160]
{
    __shared__ float sW1[64 * 32];
    __shared__ float sW2[64 * 32];
    __shared__ float2 am[8][4][64];

    int tid = threadIdx.x;
    for (int i = tid; i < 64 * 32; i += 256) {
        sW1[i] = W1[i];
        sW2[i] = W2[i];
    }
    __syncthreads();

    int warp = tid >> 5;
    int lane = tid & 31;

    const float2* ego2 = (const float2*)g_ego4;
    const float2* side2 = (const float2*)g_side4;

    int rbase = (blockIdx.x * 8 + warp) * 4;

    #pragma unroll
    for (int rr = 0; rr < 4; rr++) {
        int r = rbase + rr;
        if (r < N_NODES) {
            float2 e = ego2[r * 32 + lane];
            float2 s = side2[r * 32 + lane];
            am[warp][rr][2 * lane]     = make_float2(e.x + s.x, e.x * s.x);
            am[warp][rr][2 * lane + 1] = make_float2(e.y + s.y, e.y * s.y);
        }
    }
    __syncwarp();

    float bb1 = b1[lane];
    float bb2 = b2[lane];
    float acc1[4], acc2[4];
    #pragma unroll
    for (int rr = 0; rr < 4; rr++) { acc1[rr] = bb1; acc2[rr] = bb2; }

    #pragma unroll 8
    for (int k = 0; k < 64; k++) {
        float w1 = sW1[k * 32 + lane];
        float w2 = sW2[k * 32 + lane];
        #pragma unroll
        for (int rr = 0; rr < 4; rr++) {
            float2 v = am[warp][rr][k];
            acc1[rr] += v.x * w1;
            acc2[rr] += v.y * w2;
        }
    }

    #pragma unroll
    for (int rr = 0; rr < 4; rr++) {
        int r = rbase + rr;
        if (r >= N_NODES) break;
        float h = (acc1[rr] > 0.f ? acc1[rr] : 0.01f * acc1[rr])
                + (acc2[rr] > 0.f ? acc2[rr] : 0.01f * acc2[rr]);
        float ss = h * h;
        #pragma unroll
        for (int off = 16; off > 0; off >>= 1)
            ss += __shfl_xor_sync(0xFFFFFFFFu, ss, off);
        float inv = 1.f / fmaxf(sqrtf(ss), 1e-12f);
        out[r * 160 + 128 + lane] = h * inv;
    }
}

// ---------------------------------------------------------------------------
extern "C" void kernel_launch(void* const* d_in, const int* in_sizes, int n_in,
                              void* d_out, int out_size)
{
    const float* user_tab = (const float*)d_in[0];
    const float* entity_tab = (const float*)d_in[1];
    const float* A_vals = (const float*)d_in[2];
    const float* W1_1 = (const float*)d_in[3];
    const float* b1_1 = (const float*)d_in[4];
    const float* W2_1 = (const float*)d_in[5];
    const float* b2_1 = (const float*)d_in[6];
    const float* W1_2 = (const float*)d_in[7];
    const float* b1_2 = (const float*)d_in[8];
    const float* W2_2 = (const float*)d_in[9];
    const float* b2_2 = (const float*)d_in[10];
    const int* A_rows = (const int*)d_in[11];
    const int* A_cols = (const int*)d_in[12];
    float* out = (float*)d_out;

    // 1. init
    k_init<<<(N_NODES * 16 + 255) / 256, 256>>>(
        (const float4*)user_tab, (const float4*)entity_tab, (float4*)out);
    // 2. spmm 1
    {
        long long total = (long long)N_EDGES * 8;
        k_spmm<<<(int)((total + 255) / 256), 256>>>(A_rows, A_cols, A_vals);
    }
    // 3. bi layer 1 (zeros side)
    k_bi1<<<(N_NODES + 31) / 32, 256>>>(W1_1, b1_1, W2_1, b2_1, out);
    // 4. spmm 2
    {
        long long total = (long long)N_EDGES * 8;
        k_spmm<<<(int)((total + 255) / 256), 256>>>(A_rows, A_cols, A_vals);
    }
    // 5. bi layer 2
    k_bi2<<<(N_NODES + 31) / 32, 256>>>(W1_2, b1_2, W2_2, b2_2, out);
}

// round 3
// speedup vs baseline: 1.5580x; 1.4489x over previous
#include <cuda_runtime.h>
#include <cstdint>

#define N_USERS 30000
#define N_ENT   70000
#define N_NODES 100000
#define N_EDGES 1600000

#define SCAN_BS 512
#define SCAN_NB ((N_NODES + SCAN_BS - 1) / SCAN_BS)   // 196

// Scratch
__device__ float4 g_ego4[N_NODES * 16];    // N x 64 floats
__device__ float4 g_side4[N_NODES * 16];   // N x 64 floats
__device__ int  g_cnt[N_NODES];            // per-row edge counts
__device__ int  g_off[N_NODES + 1];        // CSR offsets
__device__ int  g_cur[N_NODES];            // scatter cursors
__device__ int  g_bsum[SCAN_NB];           // block sums for scan
__device__ int2 g_edges[N_EDGES];          // row-sorted (col, val-bits)

// ---------------------------------------------------------------------------
// Kernel 1: ego0 = concat(user, entity); out[:,0:64]; zero g_cnt
// ---------------------------------------------------------------------------
__global__ __launch_bounds__(256) void k_init(
    const float4* __restrict__ user4,
    const float4* __restrict__ ent4,
    float4* __restrict__ out4)          // 40 float4 per row
{
    int idx = blockIdx.x * blockDim.x + threadIdx.x;
    if (idx < N_NODES) g_cnt[idx] = 0;
    if (idx >= N_NODES * 16) return;
    int row = idx >> 4;
    int part = idx & 15;
    float4 v = (row < N_USERS) ? user4[row * 16 + part]
                               : ent4[(row - N_USERS) * 16 + part];
    g_ego4[idx] = v;
    out4[row * 40 + part] = v;
}

// ---------------------------------------------------------------------------
// Counting sort of edges by destination row
// ---------------------------------------------------------------------------
__global__ __launch_bounds__(256) void k_hist(const int* __restrict__ rows)
{
    int e = blockIdx.x * blockDim.x + threadIdx.x;
    if (e < N_EDGES) atomicAdd(&g_cnt[rows[e]], 1);
}

// s1: per-block exclusive scan of counts; block totals to g_bsum
__global__ __launch_bounds__(SCAN_BS) void k_scan1()
{
    __shared__ int sh[SCAN_BS];
    int tid = threadIdx.x;
    int i = blockIdx.x * SCAN_BS + tid;
    int v = (i < N_NODES) ? g_cnt[i] : 0;
    sh[tid] = v;
    __syncthreads();
    #pragma unroll
    for (int off = 1; off < SCAN_BS; off <<= 1) {
        int t = (tid >= off) ? sh[tid - off] : 0;
        __syncthreads();
        sh[tid] += t;
        __syncthreads();
    }
    if (i < N_NODES) g_off[i] = sh[tid] - v;       // exclusive local
    if (tid == SCAN_BS - 1) g_bsum[blockIdx.x] = sh[tid];
}

// s2: exclusive scan of the 196 block sums (single block)
__global__ __launch_bounds__(256) void k_scan2()
{
    __shared__ int sh[256];
    int tid = threadIdx.x;
    int v = (tid < SCAN_NB) ? g_bsum[tid] : 0;
    sh[tid] = v;
    __syncthreads();
    #pragma unroll
    for (int off = 1; off < 256; off <<= 1) {
        int t = (tid >= off) ? sh[tid - off] : 0;
        __syncthreads();
        sh[tid] += t;
        __syncthreads();
    }
    if (tid < SCAN_NB) g_bsum[tid] = sh[tid] - v;  // exclusive
}

// s3: add block prefix; init cursors; set sentinel
__global__ __launch_bounds__(SCAN_BS) void k_scan3()
{
    int i = blockIdx.x * SCAN_BS + threadIdx.x;
    if (i < N_NODES) {
        int o = g_off[i] + g_bsum[blockIdx.x];
        g_off[i] = o;
        g_cur[i] = o;
    }
    if (i == 0) g_off[N_NODES] = N_EDGES;
}

__global__ __launch_bounds__(256) void k_scatter(
    const int* __restrict__ rows,
    const int* __restrict__ cols,
    const float* __restrict__ vals)
{
    int e = blockIdx.x * blockDim.x + threadIdx.x;
    if (e >= N_EDGES) return;
    int pos = atomicAdd(&g_cur[rows[e]], 1);
    g_edges[pos] = make_int2(cols[e], __float_as_int(vals[e]));
}

// ---------------------------------------------------------------------------
// CSR SpMM: side[r] = sum_e vals*ego[col]. Warp per row, register accum,
// no atomics, overwrites side (no zeroing needed).
// ---------------------------------------------------------------------------
__global__ __launch_bounds__(256) void k_spmm_csr()
{
    int r = blockIdx.x * 8 + (threadIdx.x >> 5);
    if (r >= N_NODES) return;
    int lane = threadIdx.x & 31;
    int s = g_off[r];
    int e = g_off[r + 1];
    const float2* ego2 = (const float2*)g_ego4;

    float ax = 0.f, ay = 0.f;
    int i = s;
    for (; i + 1 < e; i += 2) {
        int2 cv0 = g_edges[i];
        int2 cv1 = g_edges[i + 1];
        float2 x0 = ego2[cv0.x * 32 + lane];
        float2 x1 = ego2[cv1.x * 32 + lane];
        float v0 = __int_as_float(cv0.y);
        float v1 = __int_as_float(cv1.y);
        ax = fmaf(v0, x0.x, ax);
        ay = fmaf(v0, x0.y, ay);
        ax = fmaf(v1, x1.x, ax);
        ay = fmaf(v1, x1.y, ay);
    }
    if (i < e) {
        int2 cv = g_edges[i];
        float2 x = ego2[cv.x * 32 + lane];
        float v = __int_as_float(cv.y);
        ax = fmaf(v, x.x, ax);
        ay = fmaf(v, x.y, ay);
    }
    ((float2*)g_side4)[r * 32 + lane] = make_float2(ax, ay);
}

// ---------------------------------------------------------------------------
// bi-interaction layer 1 (64 -> 64): one warp computes 4 rows.
// ---------------------------------------------------------------------------
__global__ __launch_bounds__(256) void k_bi1(
    const float* __restrict__ W1, const float* __restrict__ b1,
    const float* __restrict__ W2, const float* __restrict__ b2,
    float* __restrict__ out)
{
    __shared__ float sW1[64 * 64];
    __shared__ float sW2[64 * 64];
    __shared__ float2 am[8][4][64];

    int tid = threadIdx.x;
    for (int i = tid; i < 64 * 64; i += 256) {
        sW1[i] = W1[i];
        sW2[i] = W2[i];
    }
    __syncthreads();

    int warp = tid >> 5;
    int lane = tid & 31;
    int j0 = 2 * lane;

    float2* ego2 = (float2*)g_ego4;
    const float2* side2 = (const float2*)g_side4;

    int rbase = (blockIdx.x * 8 + warp) * 4;

    #pragma unroll
    for (int rr = 0; rr < 4; rr++) {
        int r = rbase + rr;
        if (r < N_NODES) {
            float2 e = ego2[r * 32 + lane];
            float2 s = side2[r * 32 + lane];
            am[warp][rr][2 * lane]     = make_float2(e.x + s.x, e.x * s.x);
            am[warp][rr][2 * lane + 1] = make_float2(e.y + s.y, e.y * s.y);
        }
    }
    __syncwarp();

    float b1x = b1[j0], b1y = b1[j0 + 1];
    float b2x = b2[j0], b2y = b2[j0 + 1];
    float acc1x[4], acc1y[4], acc2x[4], acc2y[4];
    #pragma unroll
    for (int rr = 0; rr < 4; rr++) {
        acc1x[rr] = b1x; acc1y[rr] = b1y;
        acc2x[rr] = b2x; acc2y[rr] = b2y;
    }

    #pragma unroll 8
    for (int k = 0; k < 64; k++) {
        float2 w1 = *(const float2*)(sW1 + k * 64 + j0);
        float2 w2 = *(const float2*)(sW2 + k * 64 + j0);
        #pragma unroll
        for (int rr = 0; rr < 4; rr++) {
            float2 v = am[warp][rr][k];
            acc1x[rr] += v.x * w1.x;
            acc1y[rr] += v.x * w1.y;
            acc2x[rr] += v.y * w2.x;
            acc2y[rr] += v.y * w2.y;
        }
    }

    #pragma unroll
    for (int rr = 0; rr < 4; rr++) {
        int r = rbase + rr;
        if (r >= N_NODES) break;
        float h0 = (acc1x[rr] > 0.f ? acc1x[rr] : 0.01f * acc1x[rr])
                 + (acc2x[rr] > 0.f ? acc2x[rr] : 0.01f * acc2x[rr]);
        float h1 = (acc1y[rr] > 0.f ? acc1y[rr] : 0.01f * acc1y[rr])
                 + (acc2y[rr] > 0.f ? acc2y[rr] : 0.01f * acc2y[rr]);
        float ss = h0 * h0 + h1 * h1;
        #pragma unroll
        for (int off = 16; off > 0; off >>= 1)
            ss += __shfl_xor_sync(0xFFFFFFFFu, ss, off);
        float inv = 1.f / fmaxf(sqrtf(ss), 1e-12f);
        h0 *= inv; h1 *= inv;
        ego2[r * 32 + lane] = make_float2(h0, h1);
        ((float2*)out)[r * 80 + 32 + lane] = make_float2(h0, h1);
    }
}

// ---------------------------------------------------------------------------
// bi-interaction layer 2 (64 -> 32)
// ---------------------------------------------------------------------------
__global__ __launch_bounds__(256) void k_bi2(
    const float* __restrict__ W1, const float* __restrict__ b1,
    const float* __restrict__ W2, const float* __restrict__ b2,
    float* __restrict__ out)
{
    __shared__ float sW1[64 * 32];
    __shared__ float sW2[64 * 32];
    __shared__ float2 am[8][4][64];

    int tid = threadIdx.x;
    for (int i = tid; i < 64 * 32; i += 256) {
        sW1[i] = W1[i];
        sW2[i] = W2[i];
    }
    __syncthreads();

    int warp = tid >> 5;
    int lane = tid & 31;

    const float2* ego2 = (const float2*)g_ego4;
    const float2* side2 = (const float2*)g_side4;

    int rbase = (blockIdx.x * 8 + warp) * 4;

    #pragma unroll
    for (int rr = 0; rr < 4; rr++) {
        int r = rbase + rr;
        if (r < N_NODES) {
            float2 e = ego2[r * 32 + lane];
            float2 s = side2[r * 32 + lane];
            am[warp][rr][2 * lane]     = make_float2(e.x + s.x, e.x * s.x);
            am[warp][rr][2 * lane + 1] = make_float2(e.y + s.y, e.y * s.y);
        }
    }
    __syncwarp();

    float bb1 = b1[lane];
    float bb2 = b2[lane];
    float acc1[4], acc2[4];
    #pragma unroll
    for (int rr = 0; rr < 4; rr++) { acc1[rr] = bb1; acc2[rr] = bb2; }

    #pragma unroll 8
    for (int k = 0; k < 64; k++) {
        float w1 = sW1[k * 32 + lane];
        float w2 = sW2[k * 32 + lane];
        #pragma unroll
        for (int rr = 0; rr < 4; rr++) {
            float2 v = am[warp][rr][k];
            acc1[rr] += v.x * w1;
            acc2[rr] += v.y * w2;
        }
    }

    #pragma unroll
    for (int rr = 0; rr < 4; rr++) {
        int r = rbase + rr;
        if (r >= N_NODES) break;
        float h = (acc1[rr] > 0.f ? acc1[rr] : 0.01f * acc1[rr])
                + (acc2[rr] > 0.f ? acc2[rr] : 0.01f * acc2[rr]);
        float ss = h * h;
        #pragma unroll
        for (int off = 16; off > 0; off >>= 1)
            ss += __shfl_xor_sync(0xFFFFFFFFu, ss, off);
        float inv = 1.f / fmaxf(sqrtf(ss), 1e-12f);
        out[r * 160 + 128 + lane] = h * inv;
    }
}

// ---------------------------------------------------------------------------
extern "C" void kernel_launch(void* const* d_in, const int* in_sizes, int n_in,
                              void* d_out, int out_size)
{
    const float* user_tab = (const float*)d_in[0];
    const float* entity_tab = (const float*)d_in[1];
    const float* A_vals = (const float*)d_in[2];
    const float* W1_1 = (const float*)d_in[3];
    const float* b1_1 = (const float*)d_in[4];
    const float* W2_1 = (const float*)d_in[5];
    const float* b2_1 = (const float*)d_in[6];
    const float* W1_2 = (const float*)d_in[7];
    const float* b1_2 = (const float*)d_in[8];
    const float* W2_2 = (const float*)d_in[9];
    const float* b2_2 = (const float*)d_in[10];
    const int* A_rows = (const int*)d_in[11];
    const int* A_cols = (const int*)d_in[12];
    float* out = (float*)d_out;

    int eg = (N_EDGES + 255) / 256;

    // init ego + out[:,0:64] + zero counts
    k_init<<<(N_NODES * 16 + 255) / 256, 256>>>(
        (const float4*)user_tab, (const float4*)entity_tab, (float4*)out);
    // counting sort edges by row
    k_hist<<<eg, 256>>>(A_rows);
    k_scan1<<<SCAN_NB, SCAN_BS>>>();
    k_scan2<<<1, 256>>>();
    k_scan3<<<SCAN_NB, SCAN_BS>>>();
    k_scatter<<<eg, 256>>>(A_rows, A_cols, A_vals);
    // layer 1
    k_spmm_csr<<<(N_NODES + 7) / 8, 256>>>();
    k_bi1<<<(N_NODES + 31) / 32, 256>>>(W1_1, b1_1, W2_1, b2_1, out);
    // layer 2
    k_spmm_csr<<<(N_NODES + 7) / 8, 256>>>();
    k_bi2<<<(N_NODES + 31) / 32, 256>>>(W1_2, b1_2, W2_2, b2_2, out);
}

// round 4
// speedup vs baseline: 1.6263x; 1.0438x over previous
#include <cuda_runtime.h>
#include <cuda_fp16.h>
#include <cstdint>

#define N_USERS 30000
#define N_ENT   70000
#define N_NODES 100000
#define N_EDGES 1600000

#define SCAN_BS 512
#define SCAN_NB ((N_NODES + SCAN_BS - 1) / SCAN_BS)   // 196

// Scratch
__device__ float4  g_egoA[N_NODES * 16];     // layer-0 ego, fp32
__device__ float2  g_egoB[N_NODES * 32];     // layer-1 ego, fp32
__device__ __half2 g_egoAh[N_NODES * 32];    // fp16 shadow (gather only)
__device__ __half2 g_egoBh[N_NODES * 32];
__device__ int  g_cnt[N_NODES];
__device__ int  g_off[N_NODES + 1];
__device__ int  g_cur[N_NODES];
__device__ int  g_bsum[SCAN_NB];
__device__ int2 g_edges[N_EDGES];            // row-sorted (col, val bits)

// ---------------------------------------------------------------------------
// k_init: ego0 (fp32 + fp16 shadow), out[:,0:64], AND edge histogram.
// g_cnt must be zeroed beforehand (cudaMemsetAsync).
// ---------------------------------------------------------------------------
__global__ __launch_bounds__(256) void k_init(
    const float4* __restrict__ user4,
    const float4* __restrict__ ent4,
    const int* __restrict__ rows,
    float4* __restrict__ out4)          // 40 float4 per row
{
    int idx = blockIdx.x * blockDim.x + threadIdx.x;
    if (idx < N_EDGES) atomicAdd(&g_cnt[rows[idx]], 1);
    if (idx >= N_NODES * 16) return;
    int row = idx >> 4;
    int part = idx & 15;
    float4 v = (row < N_USERS) ? user4[row * 16 + part]
                               : ent4[(row - N_USERS) * 16 + part];
    g_egoA[idx] = v;
    g_egoAh[row * 32 + 2 * part]     = __floats2half2_rn(v.x, v.y);
    g_egoAh[row * 32 + 2 * part + 1] = __floats2half2_rn(v.z, v.w);
    out4[row * 40 + part] = v;
}

// ---------------------------------------------------------------------------
// Counting-sort scan pipeline
// ---------------------------------------------------------------------------
__global__ __launch_bounds__(SCAN_BS) void k_scan1()
{
    __shared__ int sh[SCAN_BS];
    int tid = threadIdx.x;
    int i = blockIdx.x * SCAN_BS + tid;
    int v = (i < N_NODES) ? g_cnt[i] : 0;
    sh[tid] = v;
    __syncthreads();
    #pragma unroll
    for (int off = 1; off < SCAN_BS; off <<= 1) {
        int t = (tid >= off) ? sh[tid - off] : 0;
        __syncthreads();
        sh[tid] += t;
        __syncthreads();
    }
    if (i < N_NODES) g_off[i] = sh[tid] - v;
    if (tid == SCAN_BS - 1) g_bsum[blockIdx.x] = sh[tid];
}

__global__ __launch_bounds__(256) void k_scan2()
{
    __shared__ int sh[256];
    int tid = threadIdx.x;
    int v = (tid < SCAN_NB) ? g_bsum[tid] : 0;
    sh[tid] = v;
    __syncthreads();
    #pragma unroll
    for (int off = 1; off < 256; off <<= 1) {
        int t = (tid >= off) ? sh[tid - off] : 0;
        __syncthreads();
        sh[tid] += t;
        __syncthreads();
    }
    if (tid < SCAN_NB) g_bsum[tid] = sh[tid] - v;
}

__global__ __launch_bounds__(SCAN_BS) void k_scan3()
{
    int i = blockIdx.x * SCAN_BS + threadIdx.x;
    if (i < N_NODES) {
        int o = g_off[i] + g_bsum[blockIdx.x];
        g_off[i] = o;
        g_cur[i] = o;
    }
    if (i == 0) g_off[N_NODES] = N_EDGES;
}

__global__ __launch_bounds__(256) void k_scatter(
    const int* __restrict__ rows,
    const int* __restrict__ cols,
    const float* __restrict__ vals)
{
    int e = blockIdx.x * blockDim.x + threadIdx.x;
    if (e >= N_EDGES) return;
    int pos = atomicAdd(&g_cur[rows[e]], 1);
    g_edges[pos] = make_int2(cols[e], __float_as_int(vals[e]));
}

// ---------------------------------------------------------------------------
// Fused layer 1: spmm (CSR, fp16 gather) + bi-interaction 64->64 + l2norm.
// One warp: 4 rows. Writes ego1 (fp32 + fp16 shadow) and out[:,64:128].
// ---------------------------------------------------------------------------
__global__ __launch_bounds__(256) void k_layer1(
    const float* __restrict__ W1, const float* __restrict__ b1,
    const float* __restrict__ W2, const float* __restrict__ b2,
    float* __restrict__ out)
{
    __shared__ float sW1[64 * 64];
    __shared__ float sW2[64 * 64];
    __shared__ float2 am[8][4][64];

    int tid = threadIdx.x;
    for (int i = tid; i < 64 * 64; i += 256) {
        sW1[i] = W1[i];
        sW2[i] = W2[i];
    }
    __syncthreads();

    int warp = tid >> 5;
    int lane = tid & 31;
    int j0 = 2 * lane;
    int rbase = (blockIdx.x * 8 + warp) * 4;

    const float2* egoA2 = (const float2*)g_egoA;

    #pragma unroll
    for (int rr = 0; rr < 4; rr++) {
        int r = rbase + rr;
        if (r >= N_NODES) break;
        int s = g_off[r];
        int e = g_off[r + 1];
        float ax = 0.f, ay = 0.f;
        int i = s;
        for (; i + 3 < e; i += 4) {
            int2 cv0 = g_edges[i];
            int2 cv1 = g_edges[i + 1];
            int2 cv2 = g_edges[i + 2];
            int2 cv3 = g_edges[i + 3];
            float2 x0 = __half22float2(g_egoAh[cv0.x * 32 + lane]);
            float2 x1 = __half22float2(g_egoAh[cv1.x * 32 + lane]);
            float2 x2 = __half22float2(g_egoAh[cv2.x * 32 + lane]);
            float2 x3 = __half22float2(g_egoAh[cv3.x * 32 + lane]);
            float v0 = __int_as_float(cv0.y);
            float v1 = __int_as_float(cv1.y);
            float v2 = __int_as_float(cv2.y);
            float v3 = __int_as_float(cv3.y);
            ax = fmaf(v0, x0.x, ax); ay = fmaf(v0, x0.y, ay);
            ax = fmaf(v1, x1.x, ax); ay = fmaf(v1, x1.y, ay);
            ax = fmaf(v2, x2.x, ax); ay = fmaf(v2, x2.y, ay);
            ax = fmaf(v3, x3.x, ax); ay = fmaf(v3, x3.y, ay);
        }
        for (; i < e; i++) {
            int2 cv = g_edges[i];
            float2 x = __half22float2(g_egoAh[cv.x * 32 + lane]);
            float v = __int_as_float(cv.y);
            ax = fmaf(v, x.x, ax); ay = fmaf(v, x.y, ay);
        }
        float2 eg = egoA2[r * 32 + lane];
        am[warp][rr][2 * lane]     = make_float2(eg.x + ax, eg.x * ax);
        am[warp][rr][2 * lane + 1] = make_float2(eg.y + ay, eg.y * ay);
    }
    __syncwarp();

    float b1x = b1[j0], b1y = b1[j0 + 1];
    float b2x = b2[j0], b2y = b2[j0 + 1];
    float acc1x[4], acc1y[4], acc2x[4], acc2y[4];
    #pragma unroll
    for (int rr = 0; rr < 4; rr++) {
        acc1x[rr] = b1x; acc1y[rr] = b1y;
        acc2x[rr] = b2x; acc2y[rr] = b2y;
    }

    #pragma unroll 8
    for (int k = 0; k < 64; k++) {
        float2 w1 = *(const float2*)(sW1 + k * 64 + j0);
        float2 w2 = *(const float2*)(sW2 + k * 64 + j0);
        #pragma unroll
        for (int rr = 0; rr < 4; rr++) {
            float2 v = am[warp][rr][k];
            acc1x[rr] += v.x * w1.x;
            acc1y[rr] += v.x * w1.y;
            acc2x[rr] += v.y * w2.x;
            acc2y[rr] += v.y * w2.y;
        }
    }

    #pragma unroll
    for (int rr = 0; rr < 4; rr++) {
        int r = rbase + rr;
        if (r >= N_NODES) break;
        float h0 = (acc1x[rr] > 0.f ? acc1x[rr] : 0.01f * acc1x[rr])
                 + (acc2x[rr] > 0.f ? acc2x[rr] : 0.01f * acc2x[rr]);
        float h1 = (acc1y[rr] > 0.f ? acc1y[rr] : 0.01f * acc1y[rr])
                 + (acc2y[rr] > 0.f ? acc2y[rr] : 0.01f * acc2y[rr]);
        float ss = h0 * h0 + h1 * h1;
        #pragma unroll
        for (int off = 16; off > 0; off >>= 1)
            ss += __shfl_xor_sync(0xFFFFFFFFu, ss, off);
        float inv = 1.f / fmaxf(sqrtf(ss), 1e-12f);
        h0 *= inv; h1 *= inv;
        g_egoB[r * 32 + lane] = make_float2(h0, h1);
        g_egoBh[r * 32 + lane] = __floats2half2_rn(h0, h1);
        ((float2*)out)[r * 80 + 32 + lane] = make_float2(h0, h1);
    }
}

// ---------------------------------------------------------------------------
// Fused layer 2: spmm (fp16 gather from ego1) + bi-interaction 64->32.
// ---------------------------------------------------------------------------
__global__ __launch_bounds__(256) void k_layer2(
    const float* __restrict__ W1, const float* __restrict__ b1,
    const float* __restrict__ W2, const float* __restrict__ b2,
    float* __restrict__ out)
{
    __shared__ float sW1[64 * 32];
    __shared__ float sW2[64 * 32];
    __shared__ float2 am[8][4][64];

    int tid = threadIdx.x;
    for (int i = tid; i < 64 * 32; i += 256) {
        sW1[i] = W1[i];
        sW2[i] = W2[i];
    }
    __syncthreads();

    int warp = tid >> 5;
    int lane = tid & 31;
    int rbase = (blockIdx.x * 8 + warp) * 4;

    #pragma unroll
    for (int rr = 0; rr < 4; rr++) {
        int r = rbase + rr;
        if (r >= N_NODES) break;
        int s = g_off[r];
        int e = g_off[r + 1];
        float ax = 0.f, ay = 0.f;
        int i = s;
        for (; i + 3 < e; i += 4) {
            int2 cv0 = g_edges[i];
            int2 cv1 = g_edges[i + 1];
            int2 cv2 = g_edges[i + 2];
            int2 cv3 = g_edges[i + 3];
            float2 x0 = __half22float2(g_egoBh[cv0.x * 32 + lane]);
            float2 x1 = __half22float2(g_egoBh[cv1.x * 32 + lane]);
            float2 x2 = __half22float2(g_egoBh[cv2.x * 32 + lane]);
            float2 x3 = __half22float2(g_egoBh[cv3.x * 32 + lane]);
            float v0 = __int_as_float(cv0.y);
            float v1 = __int_as_float(cv1.y);
            float v2 = __int_as_float(cv2.y);
            float v3 = __int_as_float(cv3.y);
            ax = fmaf(v0, x0.x, ax); ay = fmaf(v0, x0.y, ay);
            ax = fmaf(v1, x1.x, ax); ay = fmaf(v1, x1.y, ay);
            ax = fmaf(v2, x2.x, ax); ay = fmaf(v2, x2.y, ay);
            ax = fmaf(v3, x3.x, ax); ay = fmaf(v3, x3.y, ay);
        }
        for (; i < e; i++) {
            int2 cv = g_edges[i];
            float2 x = __half22float2(g_egoBh[cv.x * 32 + lane]);
            float v = __int_as_float(cv.y);
            ax = fmaf(v, x.x, ax); ay = fmaf(v, x.y, ay);
        }
        float2 eg = g_egoB[r * 32 + lane];
        am[warp][rr][2 * lane]     = make_float2(eg.x + ax, eg.x * ax);
        am[warp][rr][2 * lane + 1] = make_float2(eg.y + ay, eg.y * ay);
    }
    __syncwarp();

    float bb1 = b1[lane];
    float bb2 = b2[lane];
    float acc1[4], acc2[4];
    #pragma unroll
    for (int rr = 0; rr < 4; rr++) { acc1[rr] = bb1; acc2[rr] = bb2; }

    #pragma unroll 8
    for (int k = 0; k < 64; k++) {
        float w1 = sW1[k * 32 + lane];
        float w2 = sW2[k * 32 + lane];
        #pragma unroll
        for (int rr = 0; rr < 4; rr++) {
            float2 v = am[warp][rr][k];
            acc1[rr] += v.x * w1;
            acc2[rr] += v.y * w2;
        }
    }

    #pragma unroll
    for (int rr = 0; rr < 4; rr++) {
        int r = rbase + rr;
        if (r >= N_NODES) break;
        float h = (acc1[rr] > 0.f ? acc1[rr] : 0.01f * acc1[rr])
                + (acc2[rr] > 0.f ? acc2[rr] : 0.01f * acc2[rr]);
        float ss = h * h;
        #pragma unroll
        for (int off = 16; off > 0; off >>= 1)
            ss += __shfl_xor_sync(0xFFFFFFFFu, ss, off);
        float inv = 1.f / fmaxf(sqrtf(ss), 1e-12f);
        out[r * 160 + 128 + lane] = h * inv;
    }
}

// ---------------------------------------------------------------------------
extern "C" void kernel_launch(void* const* d_in, const int* in_sizes, int n_in,
                              void* d_out, int out_size)
{
    const float* user_tab = (const float*)d_in[0];
    const float* entity_tab = (const float*)d_in[1];
    const float* A_vals = (const float*)d_in[2];
    const float* W1_1 = (const float*)d_in[3];
    const float* b1_1 = (const float*)d_in[4];
    const float* W2_1 = (const float*)d_in[5];
    const float* b2_1 = (const float*)d_in[6];
    const float* W1_2 = (const float*)d_in[7];
    const float* b1_2 = (const float*)d_in[8];
    const float* W2_2 = (const float*)d_in[9];
    const float* b2_2 = (const float*)d_in[10];
    const int* A_rows = (const int*)d_in[11];
    const int* A_cols = (const int*)d_in[12];
    float* out = (float*)d_out;

    int eg = (N_EDGES + 255) / 256;

    void* cnt_ptr = nullptr;
    cudaGetSymbolAddress(&cnt_ptr, g_cnt);
    cudaMemsetAsync(cnt_ptr, 0, N_NODES * sizeof(int));

    // init ego (fp32 + fp16) + out[:,0:64] + edge histogram
    k_init<<<(N_NODES * 16 + 255) / 256, 256>>>(
        (const float4*)user_tab, (const float4*)entity_tab, A_rows, (float4*)out);
    // counting sort by destination row
    k_scan1<<<SCAN_NB, SCAN_BS>>>();
    k_scan2<<<1, 256>>>();
    k_scan3<<<SCAN_NB, SCAN_BS>>>();
    k_scatter<<<eg, 256>>>(A_rows, A_cols, A_vals);
    // fused layers
    k_layer1<<<(N_NODES + 31) / 32, 256>>>(W1_1, b1_1, W2_1, b2_1, out);
    k_layer2<<<(N_NODES + 31) / 32, 256>>>(W1_2, b1_2, W2_2, b2_2, out);
}